// round 1
// baseline (speedup 1.0000x reference)
#include <cuda_runtime.h>
#include <cuda_bf16.h>
#include <math.h>

// Problem constants
#define B_SZ 8
#define T_SZ 2048
#define C_SZ 1024
#define H_SZ 64
#define WIN 64
#define NGLOB 64
#define NRAND 64

#define BT (B_SZ * T_SZ)          // 16384 rows

// Scratch for projected q, k, v  (4 MB each) — device globals, no allocation.
__device__ float g_Q[BT * H_SZ];
__device__ float g_K[BT * H_SZ];
__device__ float g_V[BT * H_SZ];

// ---------------------------------------------------------------------------
// Projection GEMM:  out[m][h] = sum_c x[m][c] * W[h][c]
// M = 16384, K = 1024, N = 64.  blockIdx.y in {0,1,2} selects (Wq,Wk,Wv).
// Tile: 64(M) x 64(N) x 32(K), 256 threads, 4x4 register microtile,
// float2 shared loads along K so the FFMA pipe (not LDS) is the binder.
// ---------------------------------------------------------------------------
#define BM 64
#define BK 32

__global__ __launch_bounds__(256) void proj_kernel(
    const float* __restrict__ x,
    const float* __restrict__ Wq,
    const float* __restrict__ Wk,
    const float* __restrict__ Wv)
{
    __shared__ float xs[BM][BK + 2];
    __shared__ float ws[H_SZ][BK + 2];

    const float* W;
    float* out;
    if (blockIdx.y == 0)      { W = Wq; out = g_Q; }
    else if (blockIdx.y == 1) { W = Wk; out = g_K; }
    else                      { W = Wv; out = g_V; }

    const int m0  = blockIdx.x * BM;
    const int tid = threadIdx.x;
    const int ty  = tid >> 4;   // 0..15
    const int tx  = tid & 15;   // 0..15

    float acc[4][4];
#pragma unroll
    for (int i = 0; i < 4; i++)
#pragma unroll
        for (int j = 0; j < 4; j++) acc[i][j] = 0.f;

    for (int ck = 0; ck < C_SZ; ck += BK) {
        // cooperative loads: 64x32 each, coalesced 128B rows
#pragma unroll
        for (int l = tid; l < BM * BK; l += 256) {
            int row = l >> 5, col = l & 31;
            xs[row][col] = x[(size_t)(m0 + row) * C_SZ + ck + col];
            ws[row][col] = W[(size_t)row * C_SZ + ck + col];
        }
        __syncthreads();

#pragma unroll
        for (int kk = 0; kk < BK; kk += 2) {
            float2 a[4], b[4];
#pragma unroll
            for (int i = 0; i < 4; i++) {
                a[i] = *(const float2*)&xs[ty * 4 + i][kk];
                b[i] = *(const float2*)&ws[tx * 4 + i][kk];
            }
#pragma unroll
            for (int i = 0; i < 4; i++)
#pragma unroll
                for (int j = 0; j < 4; j++) {
                    acc[i][j] += a[i].x * b[j].x;
                    acc[i][j] += a[i].y * b[j].y;
                }
        }
        __syncthreads();
    }

#pragma unroll
    for (int i = 0; i < 4; i++)
#pragma unroll
        for (int j = 0; j < 4; j++)
            out[(size_t)(m0 + ty * 4 + i) * H_SZ + tx * 4 + j] = acc[i][j];
}

// ---------------------------------------------------------------------------
// Sparse BigBird attention: one 256-thread block per (b, row).
// Column set: local window [lo, r] (nl entries), global [0, ng) with
// ng = min(64, lo) (excludes local overlap), random cols deduped and
// restricted to [ng, lo) (anything outside is already covered or non-causal).
// ---------------------------------------------------------------------------
__global__ __launch_bounds__(256) void attn_kernel(
    const int* __restrict__ random_cols,
    float* __restrict__ out)
{
    const int g = blockIdx.x;          // 0 .. BT-1
    const int b = g >> 11;             // T = 2048
    const int r = g & (T_SZ - 1);

    __shared__ int   cols[192];
    __shared__ float sc[192];
    __shared__ float qs[H_SZ];
    __shared__ int   rnd[NRAND];
    __shared__ int   s_nrand;
    __shared__ float red[8];
    __shared__ float s_mx, s_inv;
    __shared__ float outp[4][H_SZ];

    const int tid  = threadIdx.x;
    const int lane = tid & 31;
    const int warp = tid >> 5;

    if (tid < H_SZ) {
        qs[tid]  = g_Q[(size_t)g * H_SZ + tid];
        rnd[tid] = random_cols[r * NRAND + tid];
    }
    if (tid == 0) s_nrand = 0;

    const int lo = max(0, r - (WIN - 1));
    const int nl = r - lo + 1;              // local count (<=64)
    const int ng = min(NGLOB, lo);          // global count (no local overlap)

    __syncthreads();

    if (tid < nl)                 cols[tid] = lo + tid;
    if (tid >= 64 && tid < 64 + ng) cols[nl + (tid - 64)] = tid - 64;
    if (tid >= 128 && tid < 128 + NRAND) {
        int i = tid - 128;
        int c = rnd[i];
        bool valid = (c >= ng) && (c < lo);   // causal + not already covered
        if (valid) {
            for (int j = 0; j < i; j++)
                if (rnd[j] == c) { valid = false; break; }
        }
        if (valid) {
            int p = atomicAdd(&s_nrand, 1);
            cols[nl + ng + p] = c;
        }
    }
    __syncthreads();
    const int n = nl + ng + s_nrand;

    // ---- scores: warp per column (strided), float2 K loads, shfl reduce ----
    const float q0 = qs[lane * 2];
    const float q1 = qs[lane * 2 + 1];
    const size_t bbase = (size_t)b * T_SZ;

    for (int ci = warp; ci < n; ci += 8) {
        int c = cols[ci];
        float2 k2 = *(const float2*)&g_K[(bbase + c) * H_SZ + lane * 2];
        float p = q0 * k2.x + q1 * k2.y;
        p += __shfl_xor_sync(0xffffffffu, p, 16);
        p += __shfl_xor_sync(0xffffffffu, p, 8);
        p += __shfl_xor_sync(0xffffffffu, p, 4);
        p += __shfl_xor_sync(0xffffffffu, p, 2);
        p += __shfl_xor_sync(0xffffffffu, p, 1);
        if (lane == 0) sc[ci] = p * 0.125f;   // 1/sqrt(64)
    }
    __syncthreads();

    // ---- softmax: max ----
    float mx = -1e30f;
    for (int i = tid; i < n; i += 256) mx = fmaxf(mx, sc[i]);
#pragma unroll
    for (int o = 16; o; o >>= 1) mx = fmaxf(mx, __shfl_xor_sync(0xffffffffu, mx, o));
    if (lane == 0) red[warp] = mx;
    __syncthreads();
    if (tid == 0) {
        float m = red[0];
#pragma unroll
        for (int w = 1; w < 8; w++) m = fmaxf(m, red[w]);
        s_mx = m;
    }
    __syncthreads();
    const float smx = s_mx;

    // ---- exp + sum ----
    float sm = 0.f;
    for (int i = tid; i < n; i += 256) {
        float e = __expf(sc[i] - smx);
        sc[i] = e;
        sm += e;
    }
#pragma unroll
    for (int o = 16; o; o >>= 1) sm += __shfl_xor_sync(0xffffffffu, sm, o);
    if (lane == 0) red[warp] = sm;
    __syncthreads();
    if (tid == 0) {
        float s = 0.f;
#pragma unroll
        for (int w = 0; w < 8; w++) s += red[w];
        s_inv = 1.0f / s;
    }
    __syncthreads();
    const float inv = s_inv;

    // ---- output: 4 groups of 64 threads, each group strides over columns ----
    const int d  = tid & 63;
    const int gq = tid >> 6;
    float acc = 0.f;
    for (int i = gq; i < n; i += 4)
        acc += sc[i] * g_V[(bbase + cols[i]) * H_SZ + d];
    outp[gq][d] = acc;
    __syncthreads();

    if (tid < H_SZ) {
        float o = (outp[0][tid] + outp[1][tid] + outp[2][tid] + outp[3][tid]) * inv;
        out[(size_t)g * H_SZ + tid] = o;
    }
}

// ---------------------------------------------------------------------------
// kernel_launch — inputs per metadata order: x, random_cols, Wk, Wq, Wv
// ---------------------------------------------------------------------------
extern "C" void kernel_launch(void* const* d_in, const int* in_sizes, int n_in,
                              void* d_out, int out_size)
{
    const float* x           = (const float*)d_in[0];
    const int*   random_cols = (const int*)  d_in[1];
    const float* Wk          = (const float*)d_in[2];
    const float* Wq          = (const float*)d_in[3];
    const float* Wv          = (const float*)d_in[4];
    float* out = (float*)d_out;

    dim3 pgrid(BT / BM, 3);
    proj_kernel<<<pgrid, 256>>>(x, Wq, Wk, Wv);

    attn_kernel<<<BT, 256>>>(random_cols, out);
}

// round 3
// speedup vs baseline: 1.5023x; 1.5023x over previous
#include <cuda_runtime.h>
#include <cuda_bf16.h>
#include <math.h>
#include <stdint.h>

// Problem constants
#define B_SZ 8
#define T_SZ 2048
#define C_SZ 1024
#define H_SZ 64
#define WIN 64
#define NGLOB 64
#define NRAND 64

#define BT (B_SZ * T_SZ)          // 16384 rows

// Scratch for projected q, k, v  (4 MB each) — device globals, no allocation.
__device__ float g_Q[BT * H_SZ];
__device__ float g_K[BT * H_SZ];
__device__ float g_V[BT * H_SZ];

// ---------------------------------------------------------------------------
// tf32 helpers
// ---------------------------------------------------------------------------
__device__ __forceinline__ uint32_t f2tf32(float f) {
    uint32_t r;
    asm("cvt.rna.tf32.f32 %0, %1;" : "=r"(r) : "f"(f));
    return r;
}

__device__ __forceinline__ void mma_tf32(float* c, const uint32_t* a, const uint32_t* b) {
    asm volatile(
        "mma.sync.aligned.m16n8k8.row.col.f32.tf32.tf32.f32 "
        "{%0,%1,%2,%3}, {%4,%5,%6,%7}, {%8,%9}, {%0,%1,%2,%3};"
        : "+f"(c[0]), "+f"(c[1]), "+f"(c[2]), "+f"(c[3])
        : "r"(a[0]), "r"(a[1]), "r"(a[2]), "r"(a[3]),
          "r"(b[0]), "r"(b[1]));
}

// ---------------------------------------------------------------------------
// Projection GEMM via 3xTF32 split mma.sync:
//   out[m][h] = sum_c x[m][c] * W[h][c],  M=16384, K=1024, N=64
// Block tile: 128(M) x 64(N) x 16(K). 256 threads = 8 warps, each warp
// owns 16 M-rows x all 64 N-cols (8 n-tiles of m16n8k8).
// acc += hi*hi + lo*hi + hi*lo  (fp32 accumulate) => ~fp32 accuracy.
// smem rows padded to 20 words => fragment gather is bank-conflict-free.
// ---------------------------------------------------------------------------
#define KC 16
#define PADK 20

__global__ __launch_bounds__(256) void proj_tc_kernel(
    const float* __restrict__ x,
    const float* __restrict__ Wq,
    const float* __restrict__ Wk,
    const float* __restrict__ Wv)
{
    __shared__ uint32_t xh[128][PADK];
    __shared__ uint32_t xl[128][PADK];
    __shared__ uint32_t wh[64][PADK];
    __shared__ uint32_t wl[64][PADK];

    const float* W;
    float* out;
    if (blockIdx.y == 0)      { W = Wq; out = g_Q; }
    else if (blockIdx.y == 1) { W = Wk; out = g_K; }
    else                      { W = Wv; out = g_V; }

    const int m0   = blockIdx.x * 128;
    const int tid  = threadIdx.x;
    const int warp = tid >> 5;
    const int lane = tid & 31;
    const int grp  = lane >> 2;   // 0..7
    const int tig  = lane & 3;    // 0..3

    float acc[8][4];
#pragma unroll
    for (int nt = 0; nt < 8; nt++)
#pragma unroll
        for (int j = 0; j < 4; j++) acc[nt][j] = 0.f;

    for (int k0 = 0; k0 < C_SZ; k0 += KC) {
        // x tile: 128 rows x 16 k = 512 float4, 2 per thread
#pragma unroll
        for (int it = 0; it < 2; it++) {
            int fi  = tid + it * 256;
            int row = fi >> 2;
            int c4  = (fi & 3) * 4;
            float4 v = *(const float4*)&x[(size_t)(m0 + row) * C_SZ + k0 + c4];
            float  f[4] = {v.x, v.y, v.z, v.w};
#pragma unroll
            for (int j = 0; j < 4; j++) {
                uint32_t hi = f2tf32(f[j]);
                uint32_t lo = f2tf32(f[j] - __uint_as_float(hi));
                xh[row][c4 + j] = hi;
                xl[row][c4 + j] = lo;
            }
        }
        // W tile: 64 rows x 16 k = 256 float4, 1 per thread
        {
            int fi  = tid;
            int row = fi >> 2;
            int c4  = (fi & 3) * 4;
            float4 v = *(const float4*)&W[(size_t)row * C_SZ + k0 + c4];
            float  f[4] = {v.x, v.y, v.z, v.w};
#pragma unroll
            for (int j = 0; j < 4; j++) {
                uint32_t hi = f2tf32(f[j]);
                uint32_t lo = f2tf32(f[j] - __uint_as_float(hi));
                wh[row][c4 + j] = hi;
                wl[row][c4 + j] = lo;
            }
        }
        __syncthreads();

        const int mw = warp * 16;
#pragma unroll
        for (int kt = 0; kt < 2; kt++) {   // two k-tiles of 8
            const int kb = kt * 8;
            uint32_t ah[4], al[4];
            ah[0] = xh[mw + grp][kb + tig];
            ah[1] = xh[mw + grp + 8][kb + tig];
            ah[2] = xh[mw + grp][kb + tig + 4];
            ah[3] = xh[mw + grp + 8][kb + tig + 4];
            al[0] = xl[mw + grp][kb + tig];
            al[1] = xl[mw + grp + 8][kb + tig];
            al[2] = xl[mw + grp][kb + tig + 4];
            al[3] = xl[mw + grp + 8][kb + tig + 4];
#pragma unroll
            for (int nt = 0; nt < 8; nt++) {
                uint32_t bh[2], bl[2];
                bh[0] = wh[nt * 8 + grp][kb + tig];
                bh[1] = wh[nt * 8 + grp][kb + tig + 4];
                bl[0] = wl[nt * 8 + grp][kb + tig];
                bl[1] = wl[nt * 8 + grp][kb + tig + 4];
                mma_tf32(acc[nt], al, bh);   // lo*hi
                mma_tf32(acc[nt], ah, bl);   // hi*lo
                mma_tf32(acc[nt], ah, bh);   // hi*hi
            }
        }
        __syncthreads();
    }

    // epilogue: c0=(grp, 2*tig), c1=(grp, 2*tig+1), c2=(grp+8, 2*tig), c3=+1
    const int mw = m0 + warp * 16;
#pragma unroll
    for (int nt = 0; nt < 8; nt++) {
        int col = nt * 8 + tig * 2;
        float2 v01 = make_float2(acc[nt][0], acc[nt][1]);
        float2 v23 = make_float2(acc[nt][2], acc[nt][3]);
        *(float2*)&out[(size_t)(mw + grp) * H_SZ + col]     = v01;
        *(float2*)&out[(size_t)(mw + grp + 8) * H_SZ + col] = v23;
    }
}

// ---------------------------------------------------------------------------
// Sparse BigBird attention: one 256-thread block per (b, row).
// Column set: local window [lo, r] (nl), global [0, ng) with ng = min(64, lo)
// (excludes local overlap), random cols deduped + restricted to [ng, lo).
// Scores: 8-lane dot groups. NOTE: loop trip count is kept WARP-UNIFORM
// (ci0 strides by 32 per warp); inactive groups run the shuffles on a dummy
// column and suppress their store — full-mask shuffles stay convergent.
// ---------------------------------------------------------------------------
__global__ __launch_bounds__(256) void attn_kernel(
    const int* __restrict__ random_cols,
    float* __restrict__ out)
{
    const int g = blockIdx.x;          // 0 .. BT-1
    const int b = g >> 11;             // T = 2048
    const int r = g & (T_SZ - 1);

    __shared__ int   cols[192];
    __shared__ float sc[192];
    __shared__ __align__(16) float qs[H_SZ];
    __shared__ int   rnd[NRAND];
    __shared__ int   s_nrand;
    __shared__ float red[8];
    __shared__ float s_mx, s_inv;
    __shared__ __align__(16) float outp[16][H_SZ];

    const int tid  = threadIdx.x;
    const int lane = tid & 31;
    const int warp = tid >> 5;

    if (tid < H_SZ) {
        qs[tid]  = g_Q[(size_t)g * H_SZ + tid];
        rnd[tid] = random_cols[r * NRAND + tid];
    }
    if (tid == 0) s_nrand = 0;

    const int lo = max(0, r - (WIN - 1));
    const int nl = r - lo + 1;              // local count (<=64)
    const int ng = min(NGLOB, lo);          // global count (no local overlap)

    __syncthreads();

    if (tid < nl)                   cols[tid] = lo + tid;
    if (tid >= 64 && tid < 64 + ng) cols[nl + (tid - 64)] = tid - 64;
    if (tid >= 128 && tid < 128 + NRAND) {
        int i = tid - 128;
        int c = rnd[i];
        bool valid = (c >= ng) && (c < lo);   // causal + not already covered
        if (valid) {
            for (int j = 0; j < i; j++)
                if (rnd[j] == c) { valid = false; break; }
        }
        if (valid) {
            int p = atomicAdd(&s_nrand, 1);
            cols[nl + ng + p] = c;
        }
    }
    __syncthreads();
    const int n = nl + ng + s_nrand;

    // ---- scores: 8-lane groups, warp-uniform trip count ----
    const int l8 = lane & 7;
    const int g8 = lane >> 3;
    const float4 qa = *(const float4*)&qs[l8 * 8];
    const float4 qb = *(const float4*)&qs[l8 * 8 + 4];
    const size_t bbase = (size_t)b * T_SZ;

    for (int ci0 = warp * 4; ci0 < n; ci0 += 32) {
        int  ci  = ci0 + g8;
        bool act = (ci < n);
        int  c   = cols[act ? ci : 0];
        const float* kp = &g_K[(bbase + c) * H_SZ + l8 * 8];
        float4 ka = *(const float4*)kp;
        float4 kb = *(const float4*)(kp + 4);
        float p = qa.x * ka.x + qa.y * ka.y + qa.z * ka.z + qa.w * ka.w
                + qb.x * kb.x + qb.y * kb.y + qb.z * kb.z + qb.w * kb.w;
        p += __shfl_xor_sync(0xffffffffu, p, 4);
        p += __shfl_xor_sync(0xffffffffu, p, 2);
        p += __shfl_xor_sync(0xffffffffu, p, 1);
        if (l8 == 0 && act) sc[ci] = p * 0.125f;   // 1/sqrt(64)
    }
    __syncthreads();

    // ---- softmax: max ----
    float mx = -1e30f;
    for (int i = tid; i < n; i += 256) mx = fmaxf(mx, sc[i]);
#pragma unroll
    for (int o = 16; o; o >>= 1) mx = fmaxf(mx, __shfl_xor_sync(0xffffffffu, mx, o));
    if (lane == 0) red[warp] = mx;
    __syncthreads();
    if (tid == 0) {
        float m = red[0];
#pragma unroll
        for (int w = 1; w < 8; w++) m = fmaxf(m, red[w]);
        s_mx = m;
    }
    __syncthreads();
    const float smx = s_mx;

    // ---- exp + sum ----
    float sm = 0.f;
    for (int i = tid; i < n; i += 256) {
        float e = __expf(sc[i] - smx);
        sc[i] = e;
        sm += e;
    }
#pragma unroll
    for (int o = 16; o; o >>= 1) sm += __shfl_xor_sync(0xffffffffu, sm, o);
    if (lane == 0) red[warp] = sm;
    __syncthreads();
    if (tid == 0) {
        float s = 0.f;
#pragma unroll
        for (int w = 0; w < 8; w++) s += red[w];
        s_inv = 1.0f / s;
    }
    __syncthreads();
    const float inv = s_inv;

    // ---- output: 16 groups of 16 threads, float4 over head dim ----
    const int dg = tid & 15;
    const int gq = tid >> 4;
    float4 a4 = make_float4(0.f, 0.f, 0.f, 0.f);
    for (int i = gq; i < n; i += 16) {
        float w = sc[i];
        float4 v4 = *(const float4*)&g_V[(bbase + cols[i]) * H_SZ + dg * 4];
        a4.x += w * v4.x;
        a4.y += w * v4.y;
        a4.z += w * v4.z;
        a4.w += w * v4.w;
    }
    *(float4*)&outp[gq][dg * 4] = a4;
    __syncthreads();

    if (tid < H_SZ) {
        float o = 0.f;
#pragma unroll
        for (int k = 0; k < 16; k++) o += outp[k][tid];
        out[(size_t)g * H_SZ + tid] = o * inv;
    }
}

// ---------------------------------------------------------------------------
// kernel_launch — inputs per metadata order: x, random_cols, Wk, Wq, Wv
// ---------------------------------------------------------------------------
extern "C" void kernel_launch(void* const* d_in, const int* in_sizes, int n_in,
                              void* d_out, int out_size)
{
    const float* x           = (const float*)d_in[0];
    const int*   random_cols = (const int*)  d_in[1];
    const float* Wk          = (const float*)d_in[2];
    const float* Wq          = (const float*)d_in[3];
    const float* Wv          = (const float*)d_in[4];
    float* out = (float*)d_out;

    dim3 pgrid(BT / 128, 3);
    proj_tc_kernel<<<pgrid, 256>>>(x, Wq, Wk, Wv);

    attn_kernel<<<BT, 256>>>(random_cols, out);
}